// round 10
// baseline (speedup 1.0000x reference)
#include <cuda_runtime.h>
#include <cuda_fp16.h>
#include <cuda_fp8.h>
#include <cstdint>

// ---------------------------------------------------------------------------
// out[M,N] = (fp8(x*xs) @ fp8(w^T*ws)^T) * (1/xs)*(1/ws), fp32 out
// M=16384, N=4096, K=4096
// R10: R5 config (CTA 128x128, 8 warps 64x32, 3-stage, 2 CTA/SM) + fragment
// double-buffering with cheap addressing:
//   SWZ(row*128 + c) = row*128 + (c ^ ((row&7)<<4)),  row%8 invariant in mi
// so per-kstep address cost is 1 XOR + 1 ADD per matrix; mi offsets are
// +2048 immediates. Peeled ks loop (no branch in steady state).
// 4 launches so ncu (-s 5) lands on the GEMM.
// ---------------------------------------------------------------------------
#define MDIM 16384
#define NDIM 4096
#define KDIM 4096

#define BM 128
#define BN 128
#define BK 64                // fp16 elements per stage row (128 bytes)
#define STAGES 3
#define KITERS (KDIM / BK)   // 64

#define SWZ(o) ((o) ^ (((o) >> 3) & 0x70))

// ---------------------------------------------------------------------------
// Device scratch (allocation-free)
// ---------------------------------------------------------------------------
__device__ __align__(1024) __half g_xh[(size_t)MDIM * KDIM]; // 128 MB
__device__ __align__(1024) __half g_wh[(size_t)NDIM * KDIM]; // 32 MB
__device__ unsigned int g_amax_bits[2] = {0u, 0u};           // scale_kernel re-zeros
__device__ float g_scales[3];                                // xs, ws, (1/xs)*(1/ws)

// ---------------------------------------------------------------------------
// PTX helpers
// ---------------------------------------------------------------------------
__device__ __forceinline__ uint32_t smem_u32(const void* p) {
    uint32_t a;
    asm("{ .reg .u64 t; cvta.to.shared.u64 t, %1; cvt.u32.u64 %0, t; }" : "=r"(a) : "l"(p));
    return a;
}

#define CP_ASYNC16(dst, gsrc) \
    asm volatile("cp.async.cg.shared.global [%0], [%1], 16;" :: "r"(dst), "l"(gsrc) : "memory")
#define CP_COMMIT() asm volatile("cp.async.commit_group;" ::: "memory")
#define CP_WAIT(n)  asm volatile("cp.async.wait_group %0;" :: "n"(n) : "memory")

#define LDSM_X4(r0, r1, r2, r3, addr) \
    asm volatile("ldmatrix.sync.aligned.m8n8.x4.shared.b16 {%0,%1,%2,%3}, [%4];" \
        : "=r"(r0), "=r"(r1), "=r"(r2), "=r"(r3) : "r"(addr))

#define MMA16816(c, a, b) \
    asm volatile("mma.sync.aligned.m16n8k16.row.col.f32.f16.f16.f32 " \
        "{%0,%1,%2,%3}, {%4,%5,%6,%7}, {%8,%9}, {%0,%1,%2,%3};" \
        : "+f"((c)[0]), "+f"((c)[1]), "+f"((c)[2]), "+f"((c)[3]) \
        : "r"((a)[0]), "r"((a)[1]), "r"((a)[2]), "r"((a)[3]), "r"((b)[0]), "r"((b)[1]))

// ---------------------------------------------------------------------------
// Launch 0: fused amax (x: blocks 0..2047, w: blocks 2048..2559)
// ---------------------------------------------------------------------------
__global__ void amax_all_kernel(const float* __restrict__ x, const float* __restrict__ w) {
    int slot;
    const float4* v;
    long long n4, b0, nb;
    if (blockIdx.x < 2048) {
        slot = 0; v = (const float4*)x; n4 = (long long)MDIM * KDIM / 4; b0 = blockIdx.x; nb = 2048;
    } else {
        slot = 1; v = (const float4*)w; n4 = (long long)KDIM * NDIM / 4; b0 = blockIdx.x - 2048; nb = 512;
    }
    float m = 0.0f;
    long long stride = nb * blockDim.x;
    for (long long i = b0 * blockDim.x + threadIdx.x; i < n4; i += stride) {
        float4 a = v[i];
        m = fmaxf(m, fmaxf(fmaxf(fabsf(a.x), fabsf(a.y)), fmaxf(fabsf(a.z), fabsf(a.w))));
    }
    #pragma unroll
    for (int o = 16; o; o >>= 1) m = fmaxf(m, __shfl_xor_sync(0xFFFFFFFFu, m, o));
    __shared__ float sm[32];
    if ((threadIdx.x & 31) == 0) sm[threadIdx.x >> 5] = m;
    __syncthreads();
    if (threadIdx.x < 32) {
        m = (threadIdx.x < (blockDim.x >> 5)) ? sm[threadIdx.x] : 0.0f;
        #pragma unroll
        for (int o = 16; o; o >>= 1) m = fmaxf(m, __shfl_xor_sync(0xFFFFFFFFu, m, o));
        if (threadIdx.x == 0) atomicMax(&g_amax_bits[slot], __float_as_uint(m));
    }
}

// ---------------------------------------------------------------------------
// Launch 1: scales + reset accumulators (idempotent across graph replays)
// ---------------------------------------------------------------------------
__global__ void scale_kernel() {
    float ax = __uint_as_float(g_amax_bits[0]);
    float aw = __uint_as_float(g_amax_bits[1]);
    float xs = 448.0f / fmaxf(ax, 1e-12f);
    float ws = 448.0f / fmaxf(aw, 1e-12f);
    g_scales[0] = xs;
    g_scales[1] = ws;
    g_scales[2] = (1.0f / xs) * (1.0f / ws);
    g_amax_bits[0] = 0u;
    g_amax_bits[1] = 0u;
}

__device__ __forceinline__ unsigned short q8h(float v, float s) {
    __nv_fp8_storage_t r = __nv_cvt_float_to_fp8(v * s, __NV_SATFINITE, __NV_E4M3);
    __half_raw hr = __nv_cvt_fp8_to_halfraw(r, __NV_E4M3);
    return hr.x;
}

// ---------------------------------------------------------------------------
// Launch 2: fused quantize. Blocks [0,32768): x (8 elems/thread).
// Blocks [32768, 32768+1024): w transpose 128x128 tiles.
// ---------------------------------------------------------------------------
__global__ void quant_all_kernel(const float* __restrict__ x, const float* __restrict__ w) {
    if (blockIdx.x < 32768) {
        size_t i = ((size_t)blockIdx.x * blockDim.x + threadIdx.x) * 8;
        float s = g_scales[0];
        float4 v0 = *(const float4*)(x + i);
        float4 v1 = *(const float4*)(x + i + 4);
        uint4 packed;
        packed.x = (uint32_t)q8h(v0.x, s) | ((uint32_t)q8h(v0.y, s) << 16);
        packed.y = (uint32_t)q8h(v0.z, s) | ((uint32_t)q8h(v0.w, s) << 16);
        packed.z = (uint32_t)q8h(v1.x, s) | ((uint32_t)q8h(v1.y, s) << 16);
        packed.w = (uint32_t)q8h(v1.z, s) | ((uint32_t)q8h(v1.w, s) << 16);
        *(uint4*)(g_xh + i) = packed;
    } else {
        __shared__ unsigned short sbuf[128 * 129];
        int t = blockIdx.x - 32768;
        int k0 = (t & 31) * 128;
        int n0 = (t >> 5) * 128;
        float ws = g_scales[1];
        #pragma unroll 4
        for (int it = 0; it < 16; ++it) {
            int p = it * 1024 + threadIdx.x * 4;
            int kl = p >> 7, nl = p & 127;
            float4 v = *(const float4*)&w[(size_t)(k0 + kl) * NDIM + n0 + nl];
            sbuf[kl * 129 + nl + 0] = q8h(v.x, ws);
            sbuf[kl * 129 + nl + 1] = q8h(v.y, ws);
            sbuf[kl * 129 + nl + 2] = q8h(v.z, ws);
            sbuf[kl * 129 + nl + 3] = q8h(v.w, ws);
        }
        __syncthreads();
        #pragma unroll 2
        for (int it = 0; it < 8; ++it) {
            int tt = it * 256 + threadIdx.x;
            int nl = tt >> 4, kg = tt & 15;
            unsigned short h[8];
            #pragma unroll
            for (int i = 0; i < 8; ++i) h[i] = sbuf[(kg * 8 + i) * 129 + nl];
            uint4 packed;
            packed.x = (uint32_t)h[0] | ((uint32_t)h[1] << 16);
            packed.y = (uint32_t)h[2] | ((uint32_t)h[3] << 16);
            packed.z = (uint32_t)h[4] | ((uint32_t)h[5] << 16);
            packed.w = (uint32_t)h[6] | ((uint32_t)h[7] << 16);
            *(uint4*)(g_wh + (size_t)(n0 + nl) * KDIM + k0 + kg * 8) = packed;
        }
    }
}

// ---------------------------------------------------------------------------
// Launch 3: GEMM. A = g_xh [M,K], B = g_wh [N,K] (TN).
// CTA 128x128, 8 warps of 64x32, 3 stages, 2 CTAs/SM, double-buffered frags.
// ---------------------------------------------------------------------------
#define A_STAGE_BYTES (BM * BK * 2)          // 16384
#define B_STAGE_BYTES (BN * BK * 2)          // 16384
#define SMEM_TOTAL (STAGES * (A_STAGE_BYTES + B_STAGE_BYTES))  // 98304

__global__ void __launch_bounds__(256, 2) gemm_kernel(float* __restrict__ out) {
    extern __shared__ char smem[];
    const uint32_t sb = smem_u32(smem);
    const int tid = threadIdx.x;
    const int lane = tid & 31;
    const int wid = tid >> 5;
    const int warp_m = wid & 1;
    const int warp_n = wid >> 1;
    const int m0 = blockIdx.y * BM;
    const int n0 = blockIdx.x * BN;

    const uint64_t Ag = __cvta_generic_to_global(g_xh + (size_t)m0 * KDIM);
    const uint64_t Bg = __cvta_generic_to_global(g_wh + (size_t)n0 * KDIM);

    auto load_stage = [&](int stage, int kblk) {
        uint32_t abase = sb + stage * A_STAGE_BYTES;
        uint32_t bbase = sb + STAGES * A_STAGE_BYTES + stage * B_STAGE_BYTES;
        uint64_t koff = (uint64_t)kblk * (BK * 2);
        #pragma unroll
        for (int i = 0; i < 4; ++i) {
            int c = tid + i * 256;
            int row = c >> 3, col = c & 7;
            CP_ASYNC16(abase + SWZ(row * 128 + col * 16),
                       Ag + (uint64_t)row * (KDIM * 2) + koff + col * 16);
        }
        #pragma unroll
        for (int i = 0; i < 4; ++i) {
            int c = tid + i * 256;
            int row = c >> 3, col = c & 7;
            CP_ASYNC16(bbase + SWZ(row * 128 + col * 16),
                       Bg + (uint64_t)row * (KDIM * 2) + koff + col * 16);
        }
        CP_COMMIT();
    };

    float acc[4][4][4];
    #pragma unroll
    for (int mi = 0; mi < 4; ++mi)
        #pragma unroll
        for (int nj = 0; nj < 4; ++nj)
            #pragma unroll
            for (int r = 0; r < 4; ++r) acc[mi][nj][r] = 0.0f;

    // per-lane fragment addressing:
    // addr(mi, ks) = stage_base + a_row*128 + mi*2048 + ((ks*32 + kb) ^ pat)
    const uint32_t a_row = warp_m * 64 + (lane & 15);
    const uint32_t a_kb  = (uint32_t)((lane >> 4) << 4);
    const uint32_t a_pat = (a_row & 7) << 4;
    const uint32_t a_fix = a_row * 128;            // row base (bits >=7)
    const uint32_t b_n   = warp_n * 32 + (lane & 7) + ((lane >> 4) << 3);
    const uint32_t b_kb  = (uint32_t)(((lane >> 3) & 1) << 4);
    const uint32_t b_pat = (b_n & 7) << 4;
    const uint32_t b_fix = b_n * 128;

    uint32_t a[2][4][4], b[2][4][2];

    // prefetch frags for kstep ks from (abase,bbase) into buffer buf
    auto prefetch = [&](int buf, uint32_t abase, uint32_t bbase, int ks) {
        uint32_t pa = abase + a_fix + (((uint32_t)(ks * 32) + a_kb) ^ a_pat);
        LDSM_X4(a[buf][0][0], a[buf][0][1], a[buf][0][2], a[buf][0][3], pa);
        LDSM_X4(a[buf][1][0], a[buf][1][1], a[buf][1][2], a[buf][1][3], pa + 2048);
        LDSM_X4(a[buf][2][0], a[buf][2][1], a[buf][2][2], a[buf][2][3], pa + 4096);
        LDSM_X4(a[buf][3][0], a[buf][3][1], a[buf][3][2], a[buf][3][3], pa + 6144);
        uint32_t pb = bbase + b_fix + (((uint32_t)(ks * 32) + b_kb) ^ b_pat);
        LDSM_X4(b[buf][0][0], b[buf][0][1], b[buf][1][0], b[buf][1][1], pb);
        LDSM_X4(b[buf][2][0], b[buf][2][1], b[buf][3][0], b[buf][3][1], pb + 2048);
    };

    auto mma_all = [&](int buf) {
        #pragma unroll
        for (int mi = 0; mi < 4; ++mi)
            #pragma unroll
            for (int nj = 0; nj < 4; ++nj)
                MMA16816(acc[mi][nj], a[buf][mi], b[buf][nj]);
    };

    // prologue
    load_stage(0, 0);
    load_stage(1, 1);
    CP_WAIT(1);
    __syncthreads();
    prefetch(0, sb, sb + STAGES * A_STAGE_BYTES, 0);

    int stage = 0;
    #pragma unroll 1
    for (int it = 0; it < KITERS; ++it) {
        if (it + 2 < KITERS) {
            int ps = stage + 2;
            if (ps >= STAGES) ps -= STAGES;
            load_stage(ps, it + 2);
        }
        uint32_t abase = sb + stage * A_STAGE_BYTES;
        uint32_t bbase = sb + STAGES * A_STAGE_BYTES + stage * B_STAGE_BYTES;

        // ks = 0..2: prefetch ks+1, then MMA ks
        prefetch(1, abase, bbase, 1);
        mma_all(0);
        prefetch(0, abase, bbase, 2);
        mma_all(1);
        prefetch(1, abase, bbase, 3);
        mma_all(0);
        // ks = 3: bare
        mma_all(1);

        stage = (stage + 1 == STAGES) ? 0 : stage + 1;
        if (it + 1 < KITERS) {
            if (it + 2 < KITERS) { CP_WAIT(1); } else { CP_WAIT(0); }
            __syncthreads();
            uint32_t nabase = sb + stage * A_STAGE_BYTES;
            uint32_t nbbase = sb + STAGES * A_STAGE_BYTES + stage * B_STAGE_BYTES;
            prefetch(0, nabase, nbbase, 0);
        }
    }

    // epilogue: scale + store fp32
    const float cs = g_scales[2];
    const int row_base = m0 + warp_m * 64 + (lane >> 2);
    const int col_base = n0 + warp_n * 32 + (lane & 3) * 2;
    #pragma unroll
    for (int mi = 0; mi < 4; ++mi) {
        #pragma unroll
        for (int nj = 0; nj < 4; ++nj) {
            int r = row_base + mi * 16;
            int c = col_base + nj * 8;
            float2 v0 = make_float2(acc[mi][nj][0] * cs, acc[mi][nj][1] * cs);
            float2 v1 = make_float2(acc[mi][nj][2] * cs, acc[mi][nj][3] * cs);
            *(float2*)(out + (size_t)r * NDIM + c) = v0;
            *(float2*)(out + (size_t)(r + 8) * NDIM + c) = v1;
        }
    }
}

// ---------------------------------------------------------------------------
// Launch: exactly 4 kernels
// ---------------------------------------------------------------------------
extern "C" void kernel_launch(void* const* d_in, const int* in_sizes, int n_in,
                              void* d_out, int out_size) {
    const float* x = (const float*)d_in[0];
    const float* w = (const float*)d_in[1];
    float* out = (float*)d_out;

    cudaFuncSetAttribute(gemm_kernel, cudaFuncAttributeMaxDynamicSharedMemorySize, SMEM_TOTAL);

    amax_all_kernel<<<2560, 256>>>(x, w);
    scale_kernel<<<1, 1>>>();
    quant_all_kernel<<<32768 + 1024, 256>>>(x, w);
    gemm_kernel<<<dim3(NDIM / BN, MDIM / BM), 256, SMEM_TOTAL>>>(out);
}